// round 13
// baseline (speedup 1.0000x reference)
#include <cuda_runtime.h>
#include <cstdint>

// 2D acoustic FDTD, 500 steps, 8 shots, 256x256, 128 recs/shot.
// One persistent kernel; shot = 8-CTA cluster; field in SMEM + registers.
// R8 skeleton (one cluster.sync per step) with packed-native u64 field regs,
// ulonglong2 SMEM traffic, hoisted source injection, precomputed amp table.

#define DT 0.001f
#define DX 10.0f

constexpr int NT   = 500;
constexpr int NS   = 8;
constexpr int NZ   = 256;
constexpr int NXC  = 256;
constexpr int NREC = 128;

constexpr int CSZ  = 8;
constexpr int ROWS = NZ / CSZ;          // 32
constexpr int NTHREADS = 1024;
constexpr int COL4 = NXC / 4;           // 64
constexpr int RG   = NTHREADS / COL4;   // 16
constexpr int RPT  = ROWS / RG;         // 2

constexpr int BUF_ELEMS = ROWS * NXC;   // 8192
constexpr int OFF_AMP   = 2 * BUF_ELEMS;
constexpr size_t SMEM_BYTES = (size_t)(OFF_AMP + NT + 16) * sizeof(float);

typedef unsigned long long u64;

// ---------------------------------------------------------------- PTX helpers
__device__ __forceinline__ uint32_t cvta_smem(const void* p) {
    return (uint32_t)__cvta_generic_to_shared(p);
}
__device__ __forceinline__ uint32_t mapa_cluster(uint32_t laddr, uint32_t rank) {
    uint32_t r;
    asm("mapa.shared::cluster.u32 %0, %1, %2;" : "=r"(r) : "r"(laddr), "r"(rank));
    return r;
}
__device__ __forceinline__ ulonglong2 ld_dsmem_u64x2(uint32_t addr) {
    ulonglong2 v;
    asm volatile("ld.shared::cluster.v2.u64 {%0,%1}, [%2];"
                 : "=l"(v.x), "=l"(v.y) : "r"(addr));
    return v;
}
__device__ __forceinline__ void cluster_sync_() {
    asm volatile("barrier.cluster.arrive.aligned;" ::: "memory");
    asm volatile("barrier.cluster.wait.aligned;" ::: "memory");
}
__device__ __forceinline__ uint32_t cluster_rank_() {
    uint32_t r;
    asm("mov.u32 %0, %%cluster_ctarank;" : "=r"(r));
    return r;
}

// ---- packed f32x2 ops -------------------------------------------------------
__device__ __forceinline__ u64 pk(float a, float b) {
    u64 r; asm("mov.b64 %0, {%1, %2};" : "=l"(r) : "f"(a), "f"(b)); return r;
}
__device__ __forceinline__ float2 upk(u64 v) {
    float2 f; asm("mov.b64 {%0, %1}, %2;" : "=f"(f.x), "=f"(f.y) : "l"(v)); return f;
}
__device__ __forceinline__ u64 addx2(u64 a, u64 b) {
    u64 r; asm("add.rn.f32x2 %0, %1, %2;" : "=l"(r) : "l"(a), "l"(b)); return r;
}
__device__ __forceinline__ u64 mulx2(u64 a, u64 b) {
    u64 r; asm("mul.rn.f32x2 %0, %1, %2;" : "=l"(r) : "l"(a), "l"(b)); return r;
}
__device__ __forceinline__ u64 fmax2(u64 a, u64 b, u64 c) {
    u64 r; asm("fma.rn.f32x2 %0, %1, %2, %3;" : "=l"(r) : "l"(a), "l"(b), "l"(c)); return r;
}

// ---------------------------------------------------------------- kernel
__global__ void __cluster_dims__(CSZ, 1, 1) __launch_bounds__(NTHREADS, 1)
wave_kernel(const float* __restrict__ x,     // (NT, NS)
            const float* __restrict__ vp,    // (NZ, NXC)
            const int*   __restrict__ src,   // (NS, 2)
            const int*   __restrict__ rec,   // (NS, NREC, 2)
            float*       __restrict__ out)   // (NT, NS, NREC)
{
    extern __shared__ float sm[];
    float* buf0  = sm;
    float* buf1  = sm + BUF_ELEMS;
    float* amp_s = sm + OFF_AMP;

    __shared__ int rcnt;
    __shared__ int2 rlist[NREC];

    const int tid  = threadIdx.x;
    const uint32_t rank = cluster_rank_();
    const int shot = blockIdx.x / CSZ;

    const int col4 = tid & (COL4 - 1);
    const int rg   = tid >> 6;           // 0..15
    const int lr0  = rg * RPT;
    const int xcol = col4 * 4;
    const bool has_n = (rank > 0);
    const bool has_s = (rank < CSZ - 1);

    // --- init ----------------------------------------------------------------
    for (int i = tid; i < BUF_ELEMS; i += NTHREADS) { buf0[i] = 0.f; buf1[i] = 0.f; }
    for (int i = tid; i < NT; i += NTHREADS) {
        const int toff = (i + 2 < NT - 1) ? i + 2 : NT - 1;
        amp_s[i] = x[i * NS + shot] + x[toff * NS + shot];
    }
    if (tid == 0) rcnt = 0;
    __syncthreads();

    // claim receivers owned by this CTA
    if (tid < NREC) {
        const int gi = shot * NREC + tid;
        const int rz = rec[gi * 2 + 0];
        const int rx = rec[gi * 2 + 1];
        if ((uint32_t)(rz >> 5) == rank) {
            int s = atomicAdd(&rcnt, 1);
            rlist[s] = make_int2((rz & 31) * NXC + rx, shot * NREC + tid);
        }
    }

    // c2 in packed registers
    u64 k01[RPT], k23[RPT];
    const float sc = DT / DX;
#pragma unroll
    for (int j = 0; j < RPT; j++) {
        const int g = (int)rank * ROWS + lr0 + j;
        float4 v = *(const float4*)(vp + g * NXC + xcol);
        float a = v.x * sc, b = v.y * sc, c = v.z * sc, d = v.w * sc;
        k01[j] = pk(a * a, b * b);
        k23[j] = pk(c * c, d * d);
    }

    const u64 TWO2 = pk(2.f, 2.f);
    const u64 NEG4 = pk(-4.f, -4.f);
    const u64 NEG1 = pk(-1.f, -1.f);

    // packed-native field registers: cur pairs + negated prev pairs (zero @t=0)
    u64 c01[RPT], c23[RPT], np01[RPT], np23[RPT];
#pragma unroll
    for (int j = 0; j < RPT; j++) {
        c01[j] = 0; c23[j] = 0; np01[j] = 0; np23[j] = 0;
    }

    // source ownership (single thread in the cluster)
    const int sz = src[shot * 2 + 0];
    const int sx = src[shot * 2 + 1];
    const int sj = sz - ((int)rank * ROWS + lr0);
    const bool shere = (sj >= 0 && sj < RPT && sx >= xcol && sx < xcol + 4);
    const int scomp = sx - xcol;
    const int spatch = (sj >= 0 && sj < RPT) ? (lr0 + sj) * NXC + sx : 0;

    // DSMEM halo addresses (both parities)
    const uint32_t sa0 = cvta_smem(buf0);
    const uint32_t sa1 = cvta_smem(buf1);
    uint32_t nh0 = 0, nh1 = 0, sh0 = 0, sh1 = 0;
    if (rg == 0 && has_n) {
        const uint32_t off = (uint32_t)((ROWS - 1) * NXC + xcol) * 4u;
        nh0 = mapa_cluster(sa0 + off, rank - 1);
        nh1 = mapa_cluster(sa1 + off, rank - 1);
    }
    if (rg == RG - 1 && has_s) {
        const uint32_t off = (uint32_t)(xcol) * 4u;
        sh0 = mapa_cluster(sa0 + off, rank + 1);
        sh1 = mapa_cluster(sa1 + off, rank + 1);
    }

    __syncthreads();
    const bool samp = (tid < rcnt);
    int roff = 0;
    float* outp = out;
    if (samp) {
        int2 e = rlist[tid];
        roff = e.x;
        outp = out + e.y;
    }

    cluster_sync_();  // zeroed buffers visible cluster-wide

    // --- one FDTD step (packed-native) ---------------------------------------
    auto step = [&](const float* __restrict__ cur, float* __restrict__ nxt,
                    uint32_t nh, uint32_t sh, int t) {
        // row above the strip (pairs)
        u64 n01, n23;
        if (rg == 0) {
            if (has_n) { ulonglong2 v = ld_dsmem_u64x2(nh); n01 = v.x; n23 = v.y; }
            else       { n01 = 0; n23 = 0; }
        } else {
            ulonglong2 v = *(const ulonglong2*)(cur + (lr0 - 1) * NXC + xcol);
            n01 = v.x; n23 = v.y;
        }

#pragma unroll
        for (int j = 0; j < RPT; j++) {
            const int lr = lr0 + j;
            const u64 cv01 = c01[j], cv23 = c23[j];

            u64 s01, s23;
            if (j < RPT - 1) {
                s01 = c01[j + 1]; s23 = c23[j + 1];
            } else if (rg == RG - 1) {
                if (has_s) { ulonglong2 v = ld_dsmem_u64x2(sh); s01 = v.x; s23 = v.y; }
                else       { s01 = 0; s23 = 0; }
            } else {
                ulonglong2 v = *(const ulonglong2*)(cur + (lr + 1) * NXC + xcol);
                s01 = v.x; s23 = v.y;
            }

            const float lft = (xcol > 0)       ? cur[lr * NXC + xcol - 1] : 0.f;
            const float rgt = (xcol + 4 < NXC) ? cur[lr * NXC + xcol + 4] : 0.f;

            const float2 clo = upk(cv01), chi = upk(cv23);
            const u64 L0 = pk(lft,   clo.x);
            const u64 M  = pk(clo.y, chi.x);
            const u64 R1 = pk(chi.y, rgt);

            u64 lap01 = addx2(addx2(n01, s01), addx2(L0, M));
            u64 lap23 = addx2(addx2(n23, s23), addx2(M, R1));
            lap01 = fmax2(cv01, NEG4, lap01);
            lap23 = fmax2(cv23, NEG4, lap23);

            const u64 nv01 = fmax2(k01[j], lap01, fmax2(cv01, TWO2, np01[j]));
            const u64 nv23 = fmax2(k23[j], lap23, fmax2(cv23, TWO2, np23[j]));

            np01[j] = mulx2(cv01, NEG1);
            np23[j] = mulx2(cv23, NEG1);

            ulonglong2 st; st.x = nv01; st.y = nv23;
            *(ulonglong2*)(nxt + lr * NXC + xcol) = st;

            c01[j] = nv01; c23[j] = nv23;
            n01 = cv01; n23 = cv23;
        }

        // hoisted source injection: exactly one thread per cluster
        if (shere) {
            const float amp = amp_s[t];
            nxt[spatch] += amp;                       // SMEM patch (pre-barrier)
            const u64 a01 = (scomp == 0) ? pk(amp, 0.f) : (scomp == 1) ? pk(0.f, amp) : 0;
            const u64 a23 = (scomp == 2) ? pk(amp, 0.f) : (scomp == 3) ? pk(0.f, amp) : 0;
            c01[sj] = addx2(c01[sj], a01);            // keep register mirror exact
            c23[sj] = addx2(c23[sj], a23);
        }

        cluster_sync_();  // release my stores, acquire everyone's

        if (samp) {
            *outp = nxt[roff];
            outp += NS * NREC;
        }
    };

    // --- main time loop, unrolled x2 for compile-time buffer parity ----------
    for (int t2 = 0; t2 < NT; t2 += 2) {
        step(buf0, buf1, nh0, sh0, t2);
        step(buf1, buf0, nh1, sh1, t2 + 1);
    }
}

// ---------------------------------------------------------------- launch
extern "C" void kernel_launch(void* const* d_in, const int* in_sizes, int n_in,
                              void* d_out, int out_size)
{
    const float* x   = (const float*)d_in[0];
    const float* vp  = (const float*)d_in[1];
    const int*   src = (const int*)d_in[2];
    const int*   rec = (const int*)d_in[3];
    float*       out = (float*)d_out;

    cudaFuncSetAttribute((const void*)wave_kernel,
                         cudaFuncAttributeMaxDynamicSharedMemorySize,
                         (int)SMEM_BYTES);

    wave_kernel<<<NS * CSZ, NTHREADS, SMEM_BYTES>>>(x, vp, src, rec, out);
}

// round 14
// speedup vs baseline: 1.6741x; 1.6741x over previous
#include <cuda_runtime.h>
#include <cstdint>

// 2D acoustic FDTD, 500 steps, 8 shots, 256x256, 128 recs/shot.
// One persistent kernel; shot = 8-CTA cluster; field in SMEM + registers.
// R8 skeleton (one cluster.sync per step) + packed-native u64 field regs,
// ulonglong2 SMEM traffic, precomputed amp table. Source injection stays
// in-loop with compile-time register indices (R13's dynamic-index bug fixed).

#define DT 0.001f
#define DX 10.0f

constexpr int NT   = 500;
constexpr int NS   = 8;
constexpr int NZ   = 256;
constexpr int NXC  = 256;
constexpr int NREC = 128;

constexpr int CSZ  = 8;
constexpr int ROWS = NZ / CSZ;          // 32
constexpr int NTHREADS = 1024;
constexpr int COL4 = NXC / 4;           // 64
constexpr int RG   = NTHREADS / COL4;   // 16
constexpr int RPT  = ROWS / RG;         // 2

constexpr int BUF_ELEMS = ROWS * NXC;   // 8192
constexpr int OFF_AMP   = 2 * BUF_ELEMS;
constexpr size_t SMEM_BYTES = (size_t)(OFF_AMP + NT + 16) * sizeof(float);

typedef unsigned long long u64;

// ---------------------------------------------------------------- PTX helpers
__device__ __forceinline__ uint32_t cvta_smem(const void* p) {
    return (uint32_t)__cvta_generic_to_shared(p);
}
__device__ __forceinline__ uint32_t mapa_cluster(uint32_t laddr, uint32_t rank) {
    uint32_t r;
    asm("mapa.shared::cluster.u32 %0, %1, %2;" : "=r"(r) : "r"(laddr), "r"(rank));
    return r;
}
__device__ __forceinline__ ulonglong2 ld_dsmem_u64x2(uint32_t addr) {
    ulonglong2 v;
    asm volatile("ld.shared::cluster.v2.u64 {%0,%1}, [%2];"
                 : "=l"(v.x), "=l"(v.y) : "r"(addr));
    return v;
}
__device__ __forceinline__ void cluster_sync_() {
    asm volatile("barrier.cluster.arrive.aligned;" ::: "memory");
    asm volatile("barrier.cluster.wait.aligned;" ::: "memory");
}
__device__ __forceinline__ uint32_t cluster_rank_() {
    uint32_t r;
    asm("mov.u32 %0, %%cluster_ctarank;" : "=r"(r));
    return r;
}

// ---- packed f32x2 ops -------------------------------------------------------
__device__ __forceinline__ u64 pk(float a, float b) {
    u64 r; asm("mov.b64 %0, {%1, %2};" : "=l"(r) : "f"(a), "f"(b)); return r;
}
__device__ __forceinline__ float2 upk(u64 v) {
    float2 f; asm("mov.b64 {%0, %1}, %2;" : "=f"(f.x), "=f"(f.y) : "l"(v)); return f;
}
__device__ __forceinline__ u64 addx2(u64 a, u64 b) {
    u64 r; asm("add.rn.f32x2 %0, %1, %2;" : "=l"(r) : "l"(a), "l"(b)); return r;
}
__device__ __forceinline__ u64 mulx2(u64 a, u64 b) {
    u64 r; asm("mul.rn.f32x2 %0, %1, %2;" : "=l"(r) : "l"(a), "l"(b)); return r;
}
__device__ __forceinline__ u64 fmax2(u64 a, u64 b, u64 c) {
    u64 r; asm("fma.rn.f32x2 %0, %1, %2, %3;" : "=l"(r) : "l"(a), "l"(b), "l"(c)); return r;
}

// ---------------------------------------------------------------- kernel
__global__ void __cluster_dims__(CSZ, 1, 1) __launch_bounds__(NTHREADS, 1)
wave_kernel(const float* __restrict__ x,     // (NT, NS)
            const float* __restrict__ vp,    // (NZ, NXC)
            const int*   __restrict__ src,   // (NS, 2)
            const int*   __restrict__ rec,   // (NS, NREC, 2)
            float*       __restrict__ out)   // (NT, NS, NREC)
{
    extern __shared__ float sm[];
    float* buf0  = sm;
    float* buf1  = sm + BUF_ELEMS;
    float* amp_s = sm + OFF_AMP;

    __shared__ int rcnt;
    __shared__ int2 rlist[NREC];

    const int tid  = threadIdx.x;
    const uint32_t rank = cluster_rank_();
    const int shot = blockIdx.x / CSZ;

    const int col4 = tid & (COL4 - 1);
    const int rg   = tid >> 6;           // 0..15
    const int lr0  = rg * RPT;
    const int xcol = col4 * 4;
    const bool has_n = (rank > 0);
    const bool has_s = (rank < CSZ - 1);

    // --- init ----------------------------------------------------------------
    for (int i = tid; i < BUF_ELEMS; i += NTHREADS) { buf0[i] = 0.f; buf1[i] = 0.f; }
    for (int i = tid; i < NT; i += NTHREADS) {
        const int toff = (i + 2 < NT - 1) ? i + 2 : NT - 1;
        amp_s[i] = x[i * NS + shot] + x[toff * NS + shot];
    }
    if (tid == 0) rcnt = 0;
    __syncthreads();

    // claim receivers owned by this CTA
    if (tid < NREC) {
        const int gi = shot * NREC + tid;
        const int rz = rec[gi * 2 + 0];
        const int rx = rec[gi * 2 + 1];
        if ((uint32_t)(rz >> 5) == rank) {
            int s = atomicAdd(&rcnt, 1);
            rlist[s] = make_int2((rz & 31) * NXC + rx, shot * NREC + tid);
        }
    }

    // c2 in packed registers
    u64 k01[RPT], k23[RPT];
    const float sc = DT / DX;
#pragma unroll
    for (int j = 0; j < RPT; j++) {
        const int g = (int)rank * ROWS + lr0 + j;
        float4 v = *(const float4*)(vp + g * NXC + xcol);
        float a = v.x * sc, b = v.y * sc, c = v.z * sc, d = v.w * sc;
        k01[j] = pk(a * a, b * b);
        k23[j] = pk(c * c, d * d);
    }

    const u64 TWO2 = pk(2.f, 2.f);
    const u64 NEG4 = pk(-4.f, -4.f);
    const u64 NEG1 = pk(-1.f, -1.f);

    // packed-native field registers: cur pairs + negated prev pairs (zero @t=0)
    u64 c01[RPT], c23[RPT], np01[RPT], np23[RPT];
#pragma unroll
    for (int j = 0; j < RPT; j++) {
        c01[j] = 0; c23[j] = 0; np01[j] = 0; np23[j] = 0;
    }

    // source ownership
    const int sz = src[shot * 2 + 0];
    const int sx = src[shot * 2 + 1];
    const int sj = sz - ((int)rank * ROWS + lr0);
    const bool shere = (sj >= 0 && sj < RPT && sx >= xcol && sx < xcol + 4);
    const int scomp = sx - xcol;

    // DSMEM halo addresses (both parities)
    const uint32_t sa0 = cvta_smem(buf0);
    const uint32_t sa1 = cvta_smem(buf1);
    uint32_t nh0 = 0, nh1 = 0, sh0 = 0, sh1 = 0;
    if (rg == 0 && has_n) {
        const uint32_t off = (uint32_t)((ROWS - 1) * NXC + xcol) * 4u;
        nh0 = mapa_cluster(sa0 + off, rank - 1);
        nh1 = mapa_cluster(sa1 + off, rank - 1);
    }
    if (rg == RG - 1 && has_s) {
        const uint32_t off = (uint32_t)(xcol) * 4u;
        sh0 = mapa_cluster(sa0 + off, rank + 1);
        sh1 = mapa_cluster(sa1 + off, rank + 1);
    }

    __syncthreads();
    const bool samp = (tid < rcnt);
    int roff = 0;
    float* outp = out;
    if (samp) {
        int2 e = rlist[tid];
        roff = e.x;
        outp = out + e.y;
    }

    cluster_sync_();  // zeroed buffers visible cluster-wide

    // --- one FDTD step (packed-native; static register indices only) ---------
    auto step = [&](const float* __restrict__ cur, float* __restrict__ nxt,
                    uint32_t nh, uint32_t sh, int t) {
        // row above the strip (pairs)
        u64 n01, n23;
        if (rg == 0) {
            if (has_n) { ulonglong2 v = ld_dsmem_u64x2(nh); n01 = v.x; n23 = v.y; }
            else       { n01 = 0; n23 = 0; }
        } else {
            ulonglong2 v = *(const ulonglong2*)(cur + (lr0 - 1) * NXC + xcol);
            n01 = v.x; n23 = v.y;
        }

#pragma unroll
        for (int j = 0; j < RPT; j++) {
            const int lr = lr0 + j;
            const u64 cv01 = c01[j], cv23 = c23[j];

            u64 s01, s23;
            if (j < RPT - 1) {
                s01 = c01[j + 1]; s23 = c23[j + 1];
            } else if (rg == RG - 1) {
                if (has_s) { ulonglong2 v = ld_dsmem_u64x2(sh); s01 = v.x; s23 = v.y; }
                else       { s01 = 0; s23 = 0; }
            } else {
                ulonglong2 v = *(const ulonglong2*)(cur + (lr + 1) * NXC + xcol);
                s01 = v.x; s23 = v.y;
            }

            const float lft = (xcol > 0)       ? cur[lr * NXC + xcol - 1] : 0.f;
            const float rgt = (xcol + 4 < NXC) ? cur[lr * NXC + xcol + 4] : 0.f;

            const float2 clo = upk(cv01), chi = upk(cv23);
            const u64 L0 = pk(lft,   clo.x);
            const u64 M  = pk(clo.y, chi.x);
            const u64 R1 = pk(chi.y, rgt);

            u64 lap01 = addx2(addx2(n01, s01), addx2(L0, M));
            u64 lap23 = addx2(addx2(n23, s23), addx2(M, R1));
            lap01 = fmax2(cv01, NEG4, lap01);
            lap23 = fmax2(cv23, NEG4, lap23);

            u64 nv01 = fmax2(k01[j], lap01, fmax2(cv01, TWO2, np01[j]));
            u64 nv23 = fmax2(k23[j], lap23, fmax2(cv23, TWO2, np23[j]));

            np01[j] = mulx2(cv01, NEG1);
            np23[j] = mulx2(cv23, NEG1);

            // in-loop source injection; j is an unroll constant -> static regs
            if (shere && j == sj) {
                const float amp = amp_s[t];
                float2 lo = upk(nv01), hi = upk(nv23);
                if      (scomp == 0) lo.x += amp;
                else if (scomp == 1) lo.y += amp;
                else if (scomp == 2) hi.x += amp;
                else                 hi.y += amp;
                nv01 = pk(lo.x, lo.y);
                nv23 = pk(hi.x, hi.y);
            }

            ulonglong2 st; st.x = nv01; st.y = nv23;
            *(ulonglong2*)(nxt + lr * NXC + xcol) = st;

            c01[j] = nv01; c23[j] = nv23;
            n01 = cv01; n23 = cv23;
        }

        cluster_sync_();  // release my stores, acquire everyone's

        if (samp) {
            *outp = nxt[roff];
            outp += NS * NREC;
        }
    };

    // --- main time loop, unrolled x2 for compile-time buffer parity ----------
    for (int t2 = 0; t2 < NT; t2 += 2) {
        step(buf0, buf1, nh0, sh0, t2);
        step(buf1, buf0, nh1, sh1, t2 + 1);
    }
}

// ---------------------------------------------------------------- launch
extern "C" void kernel_launch(void* const* d_in, const int* in_sizes, int n_in,
                              void* d_out, int out_size)
{
    const float* x   = (const float*)d_in[0];
    const float* vp  = (const float*)d_in[1];
    const int*   src = (const int*)d_in[2];
    const int*   rec = (const int*)d_in[3];
    float*       out = (float*)d_out;

    cudaFuncSetAttribute((const void*)wave_kernel,
                         cudaFuncAttributeMaxDynamicSharedMemorySize,
                         (int)SMEM_BYTES);

    wave_kernel<<<NS * CSZ, NTHREADS, SMEM_BYTES>>>(x, vp, src, rec, out);
}